// round 12
// baseline (speedup 1.0000x reference)
#include <cuda_runtime.h>
#include <cuda_fp16.h>
#include <cstdint>
#include <cstddef>

#define Bn 256
#define Sn 128
#define En 1024

constexpr int MT   = 48;            // 3 subtiles of 16 packed rows per CTA
constexpr int NT   = 128;           // f-columns per chunk
constexpr int KT   = 128;           // K halfs per tile (256B rows)
constexpr int NFC  = En / NT;       // 8
constexpr int NKT  = En / KT;       // 8
constexpr int TILES = NFC * NKT;    // 64
constexpr int NTHR = 384;           // 12 warps: 3 (M) x 4 (N)
constexpr int WMN  = 3;
constexpr int WNN  = 4;

constexpr int A_TILE_B = MT * KT * 2;   // 12288
constexpr int B_TILE_B = NT * KT * 2;   // 32768
constexpr int STG_B    = A_TILE_B + B_TILE_B;     // 45056
constexpr int OFF_ROWS = 2 * STG_B;               // 90112 (48 ints)
constexpr int SMEM_TOTAL = OFF_ROWS + 256;        // 90368 -> 2 CTAs/SM
constexpr int OFF_SP   = 0;          // s_part aliases stage 0 (post-loop only;
                                     // last tile 63 is odd -> reads stage 1)

constexpr int GEMM_GRID = 512;       // covers worst case Tr = 256*96 = 24576
constexpr int MAX_ROWS  = GEMM_GRID * MT;   // 24576

constexpr int XBLK  = 24;            // x-convert blocks per bag (4 rows each)

// device-global scratch (allocations are forbidden)
__device__ __half g_Wh[En * En];
__device__ __half g_xh[Bn * Sn * En];
__device__ float  g_scp[MAX_ROWS];          // packed per-row scores
__device__ int    g_rowbase[Bn + 1];        // prefix of bag lengths
__device__ int    g_row_src[MAX_ROWS];      // packed row -> b*Sn+start+r (-1 pad)

// ---------------------------------------------------------------------------
__device__ __forceinline__ void cp16(uint32_t dst, const void* src, bool pred) {
    int sz = pred ? 16 : 0;
    asm volatile("cp.async.cg.shared.global [%0], [%1], 16, %2;\n"
                 :: "r"(dst), "l"(src), "r"(sz));
}
__device__ __forceinline__ void cp_commit() {
    asm volatile("cp.async.commit_group;\n");
}
__device__ __forceinline__ void cp_wait0() {
    asm volatile("cp.async.wait_group 0;\n");
}

__device__ __forceinline__ float tanha(float x) {
    float y;
    asm("tanh.approx.f32 %0, %1;" : "=f"(y) : "f"(x));
    return y;
}

__device__ __forceinline__ void ldsm4(uint32_t& r0, uint32_t& r1,
                                      uint32_t& r2, uint32_t& r3, uint32_t addr) {
    asm volatile("ldmatrix.sync.aligned.m8n8.x4.shared.b16 {%0,%1,%2,%3}, [%4];"
                 : "=r"(r0), "=r"(r1), "=r"(r2), "=r"(r3) : "r"(addr));
}

__device__ __forceinline__ void mma16816(float* c,
                                         uint32_t a0, uint32_t a1, uint32_t a2, uint32_t a3,
                                         uint32_t b0, uint32_t b1) {
    asm volatile(
        "mma.sync.aligned.m16n8k16.row.col.f32.f16.f16.f32 "
        "{%0,%1,%2,%3},{%4,%5,%6,%7},{%8,%9},{%0,%1,%2,%3};"
        : "+f"(c[0]), "+f"(c[1]), "+f"(c[2]), "+f"(c[3])
        : "r"(a0), "r"(a1), "r"(a2), "r"(a3), "r"(b0), "r"(b1));
}

// ---------------------------------------------------------------------------
// conv + setup kernel:
//   blocks [0, 1024)                 : convert W (fp32 -> fp16)
//   blocks [1024, 1024 + Bn*XBLK)    : convert x bag rows, 4 rows/block
//   block  1024 + Bn*XBLK            : build packed row list
// ---------------------------------------------------------------------------
__global__ __launch_bounds__(256)
void conv_kernel(const float4* __restrict__ W4,
                 const float4* __restrict__ x4,
                 const int* __restrict__ doc) {
    const int bx = blockIdx.x;
    const int t  = threadIdx.x;
    if (bx < 1024) {
        int idx = bx * 256 + t;
        float4 v = W4[idx];
        __half2* o = reinterpret_cast<__half2*>(g_Wh);
        o[idx * 2]     = __floats2half2_rn(v.x, v.y);
        o[idx * 2 + 1] = __floats2half2_rn(v.z, v.w);
    } else if (bx < 1024 + Bn * XBLK) {
        const int b  = (bx - 1024) / XBLK;
        const int gq = (bx - 1024) % XBLK;      // row group: 4 rows
        const int start = doc[2 * b];
        const int end   = doc[2 * b + 1];
        __half2* o = reinterpret_cast<__half2*>(g_xh);
        #pragma unroll
        for (int i = 0; i < 4; i++) {
            int s = start + gq * 4 + i;
            if (s < end) {
                size_t base = (size_t)(b * Sn + s) * (En / 4) + t;
                float4 v = x4[base];
                o[base * 2]     = __floats2half2_rn(v.x, v.y);
                o[base * 2 + 1] = __floats2half2_rn(v.z, v.w);
            }
        }
    } else {
        // setup block: 256 threads, one per bag
        __shared__ int len_s[Bn];
        __shared__ int base_s[Bn + 1];
        const int b = t;
        const int start = doc[2 * b];
        const int len   = doc[2 * b + 1] - start;
        len_s[b] = len;
        __syncthreads();
        if (t == 0) {
            int acc = 0;
            for (int i = 0; i < Bn; i++) { base_s[i] = acc; g_rowbase[i] = acc; acc += len_s[i]; }
            base_s[Bn] = acc;
            g_rowbase[Bn] = acc;   // Tr
        }
        __syncthreads();
        const int rb = base_s[b];
        for (int r = 0; r < len; r++) {
            g_row_src[rb + r] = b * Sn + start + r;
        }
        __syncthreads();
        const int Tr = base_s[Bn];
        for (int i = Tr + t; i < MAX_ROWS; i += 256) {
            g_row_src[i] = -1;
        }
    }
}

// ---------------------------------------------------------------------------
// GEMM kernel: dense 48-packed-row M tiles, full-E sweep, writes packed
// per-row scores to g_scp. ~259 live CTAs, single 2-CTA/SM wave.
// ---------------------------------------------------------------------------
extern __shared__ char smem[];

__global__ __launch_bounds__(NTHR, 2)
void gemm_kernel(const float* __restrict__ u) {
    const int grp = blockIdx.x;
    if (grp * MT >= g_rowbase[Bn]) return;      // beyond packed rows

    const int tid  = threadIdx.x;
    const int lane = tid & 31;
    const int wid  = tid >> 5;
    const int wm   = wid % WMN;       // subtile wm: rows [wm*16, wm*16+16)
    const int wn   = wid / WMN;       // cols [wn*32, wn*32+32)
    const int g    = lane >> 2;
    const int tg   = lane & 3;

    const uint32_t smem_u32 = (uint32_t)__cvta_generic_to_shared(smem);
    float* s_part = reinterpret_cast<float*>(smem + OFF_SP);
    int*   rows_s = reinterpret_cast<int*>(smem + OFF_ROWS);

    if (tid < MT) rows_s[tid] = g_row_src[grp * MT + tid];
    __syncthreads();

    const int fa_m = tid >> 4;        // 0..23 row within 24-row band
    const int fa_c = tid & 15;        // 16B chunk in 256B row
    const int swz  = (fa_c ^ (fa_m & 7)) << 4;   // bands stride 24 (mult of 8)

    const __half* arow[2];
    bool apred[2];
    #pragma unroll
    for (int i = 0; i < 2; i++) {
        int src  = rows_s[fa_m + i * 24];
        apred[i] = (src >= 0);
        arow[i]  = g_xh + (size_t)(src < 0 ? 0 : src) * En + fa_c * 8;
    }

    auto fill_full = [&](int t) {
        const int fc = t >> 3;
        const int k0 = (t & 7) * KT;
        const uint32_t aBase = smem_u32 + (t & 1) * STG_B;
        const uint32_t bBase = aBase + A_TILE_B;
        #pragma unroll
        for (int i = 0; i < 2; i++) {           // 48 rows in 2 bands of 24
            int m = fa_m + i * 24;
            cp16(aBase + m * 256 + swz, arow[i] + k0, apred[i]);
        }
        #pragma unroll
        for (int i = 0; i < 6; i++) {           // 128 rows in 6 bands of 24
            int n = fa_m + i * 24;
            if (n < NT)
                cp16(bBase + n * 256 + swz,
                     g_Wh + (size_t)(fc * NT + n) * En + k0 + fa_c * 8, true);
        }
        cp_commit();
    };

    float acc[4][4];
    #pragma unroll
    for (int j = 0; j < 4; j++)
        #pragma unroll
        for (int i = 0; i < 4; i++) acc[j][i] = 0.0f;
    float sacc[2] = {0.f, 0.f};

    const int a_row   = (lane & 15);
    const int a_choff = (lane >> 4);
    const int b_rowin = (lane & 7) + ((lane >> 4) << 3);
    const int b_choff = ((lane >> 3) & 1);

    fill_full(0);

    for (int fc = 0; fc < NFC; fc++) {
        for (int k = 0; k < NKT; k++) {
            const int t = fc * NKT + k;
            cp_wait0();
            __syncthreads();

            const uint32_t aBase = smem_u32 + (t & 1) * STG_B;
            const uint32_t bBase = aBase + A_TILE_B;

            const bool have_next = (t + 1 < TILES);
            const int  nfc = (t + 1) >> 3;
            const int  nk0 = ((t + 1) & 7) * KT;
            const uint32_t naBase = smem_u32 + ((t + 1) & 1) * STG_B;
            const uint32_t nbBase = naBase + A_TILE_B;

            #pragma unroll
            for (int ks = 0; ks < 8; ks++) {
                // interleaved fills of tile t+1 (1 cp.async per ks)
                if (have_next) {
                    if (ks < 2) {
                        int m = fa_m + ks * 24;
                        cp16(naBase + m * 256 + swz, arow[ks] + nk0, apred[ks]);
                    } else {
                        int n = fa_m + (ks - 2) * 24;
                        if (n < NT)
                            cp16(nbBase + n * 256 + swz,
                                 g_Wh + (size_t)(nfc * NT + n) * En + nk0 + fa_c * 8, true);
                    }
                }

                // compute
                uint32_t af[4];
                {
                    int row = wm * 16 + a_row;
                    int chv = 2 * ks + a_choff;
                    uint32_t addr = aBase + row * 256 + ((chv ^ (row & 7)) << 4);
                    ldsm4(af[0], af[1], af[2], af[3], addr);
                }
                uint32_t bf[2][4];
                #pragma unroll
                for (int jp = 0; jp < 2; jp++) {
                    int nrow = wn * 32 + jp * 16 + b_rowin;
                    int chv = 2 * ks + b_choff;
                    uint32_t addr = bBase + nrow * 256 + ((chv ^ (nrow & 7)) << 4);
                    ldsm4(bf[jp][0], bf[jp][1], bf[jp][2], bf[jp][3], addr);
                }
                #pragma unroll
                for (int j = 0; j < 4; j++) {
                    mma16816(acc[j], af[0], af[1], af[2], af[3],
                             bf[j >> 1][(j & 1) * 2], bf[j >> 1][(j & 1) * 2 + 1]);
                }
            }
            cp_commit();
        }

        // f-chunk epilogue: scores += tanh(z) * u   (u via __ldg, L1-hot)
        #pragma unroll
        for (int j = 0; j < 4; j++) {
            int f = fc * NT + wn * 32 + j * 8 + 2 * tg;
            float u0 = __ldg(u + f), u1 = __ldg(u + f + 1);
            sacc[0] += tanha(acc[j][0]) * u0 + tanha(acc[j][1]) * u1;
            sacc[1] += tanha(acc[j][2]) * u0 + tanha(acc[j][3]) * u1;
            acc[j][0] = 0.f; acc[j][1] = 0.f;
            acc[j][2] = 0.f; acc[j][3] = 0.f;
        }
    }

    // deterministic tg-reduction -> s_part (aliases stage 0; last tile read stage 1)
    #pragma unroll
    for (int rg = 0; rg < 2; rg++) {
        float v = sacc[rg];
        v += __shfl_xor_sync(0xffffffffu, v, 1);
        v += __shfl_xor_sync(0xffffffffu, v, 2);
        if (tg == 0) {
            int row = wm * 16 + rg * 8 + g;
            s_part[row * WNN + wn] = v;
        }
    }
    __syncthreads();

    // warp 0 sums the 4 N-partials per row, writes packed global scores
    if (wid == 0) {
        #pragma unroll
        for (int i = 0; i < 2; i++) {
            int r = lane + 32 * i;
            if (r < MT) {
                float sv = s_part[r * WNN + 0] + s_part[r * WNN + 1] +
                           s_part[r * WNN + 2] + s_part[r * WNN + 3];
                g_scp[grp * MT + r] = sv;
            }
        }
    }
}

// ---------------------------------------------------------------------------
// Finish kernel: per-bag softmax + fp16 GEMV (unroll x4) + keep_attention.
// ---------------------------------------------------------------------------
__global__ __launch_bounds__(256)
void finish_kernel(const int* __restrict__ doc, float* __restrict__ out) {
    const int b    = blockIdx.x;
    const int tid  = threadIdx.x;
    const int lane = tid & 31;
    const int wid  = tid >> 5;

    __shared__ float attn_s[96];

    const int start = doc[2 * b];
    const int len   = doc[2 * b + 1] - start;    // 1..96
    const int rb    = g_rowbase[b];

    if (wid == 0) {
        float v[3];
        #pragma unroll
        for (int i = 0; i < 3; i++) {
            int r = lane + 32 * i;
            v[i] = (r < len) ? g_scp[rb + r] : -3.0e38f;
        }
        float mx = fmaxf(v[0], fmaxf(v[1], v[2]));
        #pragma unroll
        for (int o = 16; o > 0; o >>= 1)
            mx = fmaxf(mx, __shfl_xor_sync(0xffffffffu, mx, o));
        float e[3];
        float ssum = 0.0f;
        #pragma unroll
        for (int i = 0; i < 3; i++) {
            int r = lane + 32 * i;
            e[i] = (r < len) ? __expf(v[i] - mx) : 0.0f;
            ssum += e[i];
        }
        #pragma unroll
        for (int o = 16; o > 0; o >>= 1)
            ssum += __shfl_xor_sync(0xffffffffu, ssum, o);
        float inv = 1.0f / ssum;
        #pragma unroll
        for (int i = 0; i < 3; i++) {
            int r = lane + 32 * i;
            attn_s[r] = (r < len) ? e[i] * inv : 0.0f;
        }
    }
    __syncthreads();

    // out GEMV from fp16 x, 4-way unrolled for MLP
    {
        const uint2* xb = reinterpret_cast<const uint2*>(
            g_xh + (size_t)(b * Sn + start) * En);
        float4 a0 = make_float4(0.f, 0.f, 0.f, 0.f);
        float4 a1 = make_float4(0.f, 0.f, 0.f, 0.f);
        float4 a2 = make_float4(0.f, 0.f, 0.f, 0.f);
        float4 a3 = make_float4(0.f, 0.f, 0.f, 0.f);
        int s = 0;
        for (; s + 4 <= len; s += 4) {
            float w0 = attn_s[s],     w1 = attn_s[s + 1];
            float w2 = attn_s[s + 2], w3 = attn_s[s + 3];
            uint2 v0 = xb[(size_t)s * (En / 4) + tid];
            uint2 v1 = xb[(size_t)(s + 1) * (En / 4) + tid];
            uint2 v2 = xb[(size_t)(s + 2) * (En / 4) + tid];
            uint2 v3 = xb[(size_t)(s + 3) * (En / 4) + tid];
            float2 p0 = __half22float2(*reinterpret_cast<__half2*>(&v0.x));
            float2 p1 = __half22float2(*reinterpret_cast<__half2*>(&v0.y));
            float2 q0 = __half22float2(*reinterpret_cast<__half2*>(&v1.x));
            float2 q1 = __half22float2(*reinterpret_cast<__half2*>(&v1.y));
            float2 r0 = __half22float2(*reinterpret_cast<__half2*>(&v2.x));
            float2 r1 = __half22float2(*reinterpret_cast<__half2*>(&v2.y));
            float2 s0 = __half22float2(*reinterpret_cast<__half2*>(&v3.x));
            float2 s1 = __half22float2(*reinterpret_cast<__half2*>(&v3.y));
            a0.x += w0 * p0.x; a0.y += w0 * p0.y; a0.z += w0 * p1.x; a0.w += w0 * p1.y;
            a1.x += w1 * q0.x; a1.y += w1 * q0.y; a1.z += w1 * q1.x; a1.w += w1 * q1.y;
            a2.x += w2 * r0.x; a2.y += w2 * r0.y; a2.z += w2 * r1.x; a2.w += w2 * r1.y;
            a3.x += w3 * s0.x; a3.y += w3 * s0.y; a3.z += w3 * s1.x; a3.w += w3 * s1.y;
        }
        for (; s < len; s++) {
            float w0 = attn_s[s];
            uint2 v0 = xb[(size_t)s * (En / 4) + tid];
            float2 p0 = __half22float2(*reinterpret_cast<__half2*>(&v0.x));
            float2 p1 = __half22float2(*reinterpret_cast<__half2*>(&v0.y));
            a0.x += w0 * p0.x; a0.y += w0 * p0.y; a0.z += w0 * p1.x; a0.w += w0 * p1.y;
        }
        a0.x += a1.x + a2.x + a3.x;
        a0.y += a1.y + a2.y + a3.y;
        a0.z += a1.z + a2.z + a3.z;
        a0.w += a1.w + a2.w + a3.w;
        reinterpret_cast<float4*>(out)[(size_t)b * (En / 4) + tid] = a0;
    }

    // keep_attention (last batch only): zeros outside the bag
    if (b == Bn - 1 && tid < Sn) {
        int r = tid - start;
        out[(size_t)Bn * En + tid] = (r >= 0 && r < len) ? attn_s[r] : 0.0f;
    }
}

// ---------------------------------------------------------------------------
extern "C" void kernel_launch(void* const* d_in, const int* in_sizes, int n_in,
                              void* d_out, int out_size) {
    const float* x   = (const float*)d_in[0];
    const float* W   = (const float*)d_in[1];
    const float* u   = (const float*)d_in[2];
    const int*   doc = (const int*)d_in[3];
    float* out = (float*)d_out;

    conv_kernel<<<1024 + Bn * XBLK + 1, 256>>>((const float4*)W, (const float4*)x, doc);

    cudaFuncSetAttribute(gemm_kernel,
                         cudaFuncAttributeMaxDynamicSharedMemorySize, SMEM_TOTAL);
    gemm_kernel<<<GEMM_GRID, NTHR, SMEM_TOTAL>>>(u);

    finish_kernel<<<Bn, 256>>>(doc, out);
}

// round 13
// speedup vs baseline: 1.1138x; 1.1138x over previous
#include <cuda_runtime.h>
#include <cuda_fp16.h>
#include <cstdint>
#include <cstddef>

#define Bn 256
#define Sn 128
#define En 1024

constexpr int MT   = 64;            // 4 subtiles of 16 rows per CTA
constexpr int NT   = 128;           // f-columns per chunk
constexpr int KT   = 128;           // K halfs per tile (256B rows)
constexpr int NFC  = En / NT;       // 8
constexpr int NKT  = En / KT;       // 8
constexpr int TILES = NFC * NKT;    // 64
constexpr int NTHR = 256;           // 8 warps: 2 (M) x 4 (N)
constexpr int WMN  = 2;
constexpr int WNN  = 4;

constexpr int A_TILE_B = MT * KT * 2;   // 16384
constexpr int B_TILE_B = NT * KT * 2;   // 32768
constexpr int STG_B    = A_TILE_B + B_TILE_B;     // 49152
constexpr int OFF_ITEM = 2 * STG_B;               // 98304
constexpr int SMEM_TOTAL = OFF_ITEM + 32;         // 98336 -> 2 CTAs/SM
constexpr int OFF_SP   = 0;          // s_part aliases stage 0 (post-loop only;
                                     // last tile 63 is odd -> reads stage 1)

constexpr int GEMM_GRID = 384;       // covers worst-case T=1536
constexpr int LIVE      = 296;       // 2 x 148 SMs: uniform single wave
constexpr int MAX_ITEMS = 1536;

constexpr int XBLK  = 24;            // x-convert blocks per bag (4 rows each)
constexpr int WCONV = 512;           // W-convert blocks (2 float4 per thread)

// device-global scratch (allocations are forbidden)
__device__ __half g_Wh[En * En];
__device__ __half g_xh[Bn * Sn * En];
__device__ float  g_scp[GEMM_GRID * MT];    // per-item-row scores
__device__ int    g_itembase[Bn + 1];
__device__ int    g_item_src[MAX_ITEMS];    // b*Sn + start + st*16
__device__ int    g_item_val[MAX_ITEMS];    // valid rows in subtile (0..16)

// ---------------------------------------------------------------------------
__device__ __forceinline__ void cp16(uint32_t dst, const void* src, bool pred) {
    int sz = pred ? 16 : 0;
    asm volatile("cp.async.cg.shared.global [%0], [%1], 16, %2;\n"
                 :: "r"(dst), "l"(src), "r"(sz));
}
__device__ __forceinline__ void cp_commit() {
    asm volatile("cp.async.commit_group;\n");
}
__device__ __forceinline__ void cp_wait0() {
    asm volatile("cp.async.wait_group 0;\n");
}

__device__ __forceinline__ float tanha(float x) {
    float y;
    asm("tanh.approx.f32 %0, %1;" : "=f"(y) : "f"(x));
    return y;
}

__device__ __forceinline__ void ldsm4(uint32_t& r0, uint32_t& r1,
                                      uint32_t& r2, uint32_t& r3, uint32_t addr) {
    asm volatile("ldmatrix.sync.aligned.m8n8.x4.shared.b16 {%0,%1,%2,%3}, [%4];"
                 : "=r"(r0), "=r"(r1), "=r"(r2), "=r"(r3) : "r"(addr));
}

__device__ __forceinline__ void mma16816(float* c,
                                         uint32_t a0, uint32_t a1, uint32_t a2, uint32_t a3,
                                         uint32_t b0, uint32_t b1) {
    asm volatile(
        "mma.sync.aligned.m16n8k16.row.col.f32.f16.f16.f32 "
        "{%0,%1,%2,%3},{%4,%5,%6,%7},{%8,%9},{%0,%1,%2,%3};"
        : "+f"(c[0]), "+f"(c[1]), "+f"(c[2]), "+f"(c[3])
        : "r"(a0), "r"(a1), "r"(a2), "r"(a3), "r"(b0), "r"(b1));
}

// ---------------------------------------------------------------------------
// conv + setup kernel:
//   blocks [0, WCONV)                : convert W (2 float4 per thread, MLP=2)
//   blocks [WCONV, WCONV + Bn*XBLK)  : convert x bag rows, 4 rows/block
//   block  WCONV + Bn*XBLK           : build subtile work list (cheap, item-level)
// ---------------------------------------------------------------------------
__global__ __launch_bounds__(256)
void conv_kernel(const float4* __restrict__ W4,
                 const float4* __restrict__ x4,
                 const int* __restrict__ doc) {
    const int bx = blockIdx.x;
    const int t  = threadIdx.x;
    if (bx < WCONV) {
        __half2* o = reinterpret_cast<__half2*>(g_Wh);
        #pragma unroll
        for (int i = 0; i < 2; i++) {
            int idx = (bx * 2 + i) * 256 + t;
            float4 v = W4[idx];
            o[idx * 2]     = __floats2half2_rn(v.x, v.y);
            o[idx * 2 + 1] = __floats2half2_rn(v.z, v.w);
        }
    } else if (bx < WCONV + Bn * XBLK) {
        const int b  = (bx - WCONV) / XBLK;
        const int gq = (bx - WCONV) % XBLK;     // row group: 4 rows
        const int start = doc[2 * b];
        const int end   = doc[2 * b + 1];
        __half2* o = reinterpret_cast<__half2*>(g_xh);
        #pragma unroll
        for (int i = 0; i < 4; i++) {
            int s = start + gq * 4 + i;
            if (s < end) {
                size_t base = (size_t)(b * Sn + s) * (En / 4) + t;
                float4 v = x4[base];
                o[base * 2]     = __floats2half2_rn(v.x, v.y);
                o[base * 2 + 1] = __floats2half2_rn(v.z, v.w);
            }
        }
    } else {
        // setup block: 256 threads, one per bag
        __shared__ int nmt_s[Bn];
        const int b = t;
        const int start = doc[2 * b];
        const int len   = doc[2 * b + 1] - start;
        const int nmt   = (len + 15) >> 4;
        nmt_s[b] = nmt;
        __syncthreads();
        if (t == 0) {
            int acc = 0;
            for (int i = 0; i < Bn; i++) { g_itembase[i] = acc; acc += nmt_s[i]; }
            g_itembase[Bn] = acc;   // T
        }
        __syncthreads();
        const int base = g_itembase[b];
        for (int st = 0; st < nmt; st++) {
            int v = len - st * 16; if (v > 16) v = 16;
            g_item_src[base + st] = b * Sn + start + st * 16;
            g_item_val[base + st] = v;
        }
        __syncthreads();
        const int T = g_itembase[Bn];
        for (int i = T + t; i < MAX_ITEMS; i += 256) {
            g_item_src[i] = 0;
            g_item_val[i] = 0;
        }
    }
}

// ---------------------------------------------------------------------------
// GEMM kernel: uniform 4-subtile M tiles (work-list), full-E sweep, writes
// per-item-row score partial sums to g_scp. 296 equal CTAs, single wave.
// ---------------------------------------------------------------------------
extern __shared__ char smem[];

__global__ __launch_bounds__(NTHR, 2)
void gemm_kernel(const float* __restrict__ u) {
    const int grp = blockIdx.x;
    if (grp >= LIVE && grp * 4 >= g_itembase[Bn]) return;   // overflow guard

    const int tid  = threadIdx.x;
    const int lane = tid & 31;
    const int wid  = tid >> 5;
    const int wm   = wid % WMN;       // subtiles wm*2, wm*2+1
    const int wn   = wid / WMN;       // cols [wn*32, wn*32+32)
    const int g    = lane >> 2;
    const int tg   = lane & 3;

    const uint32_t smem_u32 = (uint32_t)__cvta_generic_to_shared(smem);
    float* s_part = reinterpret_cast<float*>(smem + OFF_SP);
    int*   item_s = reinterpret_cast<int*>(smem + OFF_ITEM);

    if (tid < 4) {
        item_s[tid]     = g_item_src[grp * 4 + tid];
        item_s[4 + tid] = g_item_val[grp * 4 + tid];
    }
    __syncthreads();

    const int fa_m = tid >> 4;        // 0..15 row within 16-row band
    const int fa_c = tid & 15;        // 16B chunk in 256B row
    const int swz  = (fa_c ^ (fa_m & 7)) << 4;   // m&7 == fa_m&7 for all bands

    const __half* arow[4];
    bool apred[4];
    #pragma unroll
    for (int i = 0; i < 4; i++) {
        arow[i]  = g_xh + (size_t)(item_s[i] + fa_m) * En + fa_c * 8;
        apred[i] = fa_m < item_s[4 + i];
    }

    auto fill_full = [&](int t) {
        const int fc = t >> 3;
        const int k0 = (t & 7) * KT;
        const uint32_t aBase = smem_u32 + (t & 1) * STG_B;
        const uint32_t bBase = aBase + A_TILE_B;
        #pragma unroll
        for (int i = 0; i < 4; i++) {
            int m = fa_m + i * 16;
            cp16(aBase + m * 256 + swz, arow[i] + k0, apred[i]);
        }
        #pragma unroll
        for (int i = 0; i < 8; i++) {
            int n = fa_m + i * 16;
            cp16(bBase + n * 256 + swz,
                 g_Wh + (size_t)(fc * NT + n) * En + k0 + fa_c * 8, true);
        }
        cp_commit();
    };

    float acc[2][4][4];
    #pragma unroll
    for (int ms = 0; ms < 2; ms++)
        #pragma unroll
        for (int j = 0; j < 4; j++)
            #pragma unroll
            for (int i = 0; i < 4; i++) acc[ms][j][i] = 0.0f;
    float sacc[2][2] = {{0.f,0.f},{0.f,0.f}};

    const int a_row   = (lane & 15);
    const int a_choff = (lane >> 4);
    const int b_rowin = (lane & 7) + ((lane >> 4) << 3);
    const int b_choff = ((lane >> 3) & 1);

    fill_full(0);

    for (int fc = 0; fc < NFC; fc++) {
        for (int k = 0; k < NKT; k++) {
            const int t = fc * NKT + k;
            cp_wait0();
            __syncthreads();

            const uint32_t aBase = smem_u32 + (t & 1) * STG_B;
            const uint32_t bBase = aBase + A_TILE_B;

            const bool have_next = (t + 1 < TILES);
            const int  nfc = (t + 1) >> 3;
            const int  nk0 = ((t + 1) & 7) * KT;
            const uint32_t naBase = smem_u32 + ((t + 1) & 1) * STG_B;
            const uint32_t nbBase = naBase + A_TILE_B;

            #pragma unroll
            for (int ks = 0; ks < 8; ks++) {
                // interleaved fills of tile t+1 (~1.5 cp.async per ks)
                if (have_next) {
                    if (ks < 4) {
                        int m = fa_m + ks * 16;
                        cp16(naBase + m * 256 + swz, arow[ks] + nk0, apred[ks]);
                    }
                    {
                        int n = fa_m + ks * 16;
                        cp16(nbBase + n * 256 + swz,
                             g_Wh + (size_t)(nfc * NT + n) * En + nk0 + fa_c * 8, true);
                    }
                }

                // compute
                uint32_t af[2][4];
                #pragma unroll
                for (int ms = 0; ms < 2; ms++) {
                    int row = (wm * 2 + ms) * 16 + a_row;
                    int chv = 2 * ks + a_choff;
                    uint32_t addr = aBase + row * 256 + ((chv ^ (row & 7)) << 4);
                    ldsm4(af[ms][0], af[ms][1], af[ms][2], af[ms][3], addr);
                }
                uint32_t bf[2][4];
                #pragma unroll
                for (int jp = 0; jp < 2; jp++) {
                    int nrow = wn * 32 + jp * 16 + b_rowin;
                    int chv = 2 * ks + b_choff;
                    uint32_t addr = bBase + nrow * 256 + ((chv ^ (nrow & 7)) << 4);
                    ldsm4(bf[jp][0], bf[jp][1], bf[jp][2], bf[jp][3], addr);
                }
                #pragma unroll
                for (int ms = 0; ms < 2; ms++) {
                    #pragma unroll
                    for (int j = 0; j < 4; j++) {
                        mma16816(acc[ms][j],
                                 af[ms][0], af[ms][1], af[ms][2], af[ms][3],
                                 bf[j >> 1][(j & 1) * 2], bf[j >> 1][(j & 1) * 2 + 1]);
                    }
                }
            }
            cp_commit();
        }

        // f-chunk epilogue: scores += tanh(z) * u   (u via __ldg, L1-hot)
        #pragma unroll
        for (int ms = 0; ms < 2; ms++) {
            #pragma unroll
            for (int j = 0; j < 4; j++) {
                int f = fc * NT + wn * 32 + j * 8 + 2 * tg;
                float u0 = __ldg(u + f), u1 = __ldg(u + f + 1);
                sacc[ms][0] += tanha(acc[ms][j][0]) * u0 + tanha(acc[ms][j][1]) * u1;
                sacc[ms][1] += tanha(acc[ms][j][2]) * u0 + tanha(acc[ms][j][3]) * u1;
                acc[ms][j][0] = 0.f; acc[ms][j][1] = 0.f;
                acc[ms][j][2] = 0.f; acc[ms][j][3] = 0.f;
            }
        }
    }

    // deterministic tg-reduction -> s_part (aliases stage 0; last tile read stage 1)
    #pragma unroll
    for (int ms = 0; ms < 2; ms++) {
        #pragma unroll
        for (int rg = 0; rg < 2; rg++) {
            float v = sacc[ms][rg];
            v += __shfl_xor_sync(0xffffffffu, v, 1);
            v += __shfl_xor_sync(0xffffffffu, v, 2);
            if (tg == 0) {
                int row = (wm * 2 + ms) * 16 + rg * 8 + g;
                s_part[row * WNN + wn] = v;
            }
        }
    }
    __syncthreads();

    // warp 0 sums the 4 N-partials per row and writes global scores
    if (wid == 0) {
        #pragma unroll
        for (int i = 0; i < 2; i++) {
            int r = lane + 32 * i;
            float sv = s_part[r * WNN + 0] + s_part[r * WNN + 1] +
                       s_part[r * WNN + 2] + s_part[r * WNN + 3];
            g_scp[grp * MT + r] = sv;
        }
    }
}

// ---------------------------------------------------------------------------
// Finish kernel: per-bag softmax + fp16 GEMV (unroll x4) + keep_attention.
// ---------------------------------------------------------------------------
__global__ __launch_bounds__(256)
void finish_kernel(const int* __restrict__ doc, float* __restrict__ out) {
    const int b    = blockIdx.x;
    const int tid  = threadIdx.x;
    const int lane = tid & 31;
    const int wid  = tid >> 5;

    __shared__ float attn_s[96];

    const int start = doc[2 * b];
    const int len   = doc[2 * b + 1] - start;    // 1..96
    const int ib    = g_itembase[b];

    if (wid == 0) {
        float v[3];
        #pragma unroll
        for (int i = 0; i < 3; i++) {
            int r = lane + 32 * i;
            v[i] = (r < len)
                 ? g_scp[(ib + (r >> 4)) * 16 + (r & 15)]
                 : -3.0e38f;
        }
        float mx = fmaxf(v[0], fmaxf(v[1], v[2]));
        #pragma unroll
        for (int o = 16; o > 0; o >>= 1)
            mx = fmaxf(mx, __shfl_xor_sync(0xffffffffu, mx, o));
        float e[3];
        float ssum = 0.0f;
        #pragma unroll
        for (int i = 0; i < 3; i++) {
            int r = lane + 32 * i;
            e[i] = (r < len) ? __expf(v[i] - mx) : 0.0f;
            ssum += e[i];
        }
        #pragma unroll
        for (int o = 16; o > 0; o >>= 1)
            ssum += __shfl_xor_sync(0xffffffffu, ssum, o);
        float inv = 1.0f / ssum;
        #pragma unroll
        for (int i = 0; i < 3; i++) {
            int r = lane + 32 * i;
            attn_s[r] = (r < len) ? e[i] * inv : 0.0f;
        }
    }
    __syncthreads();

    // out GEMV from fp16 x, 4-way unrolled for MLP
    {
        const uint2* xb = reinterpret_cast<const uint2*>(
            g_xh + (size_t)(b * Sn + start) * En);
        float4 a0 = make_float4(0.f, 0.f, 0.f, 0.f);
        float4 a1 = make_float4(0.f, 0.f, 0.f, 0.f);
        float4 a2 = make_float4(0.f, 0.f, 0.f, 0.f);
        float4 a3 = make_float4(0.f, 0.f, 0.f, 0.f);
        int s = 0;
        for (; s + 4 <= len; s += 4) {
            float w0 = attn_s[s],     w1 = attn_s[s + 1];
            float w2 = attn_s[s + 2], w3 = attn_s[s + 3];
            uint2 v0 = xb[(size_t)s * (En / 4) + tid];
            uint2 v1 = xb[(size_t)(s + 1) * (En / 4) + tid];
            uint2 v2 = xb[(size_t)(s + 2) * (En / 4) + tid];
            uint2 v3 = xb[(size_t)(s + 3) * (En / 4) + tid];
            float2 p0 = __half22float2(*reinterpret_cast<__half2*>(&v0.x));
            float2 p1 = __half22float2(*reinterpret_cast<__half2*>(&v0.y));
            float2 q0 = __half22float2(*reinterpret_cast<__half2*>(&v1.x));
            float2 q1 = __half22float2(*reinterpret_cast<__half2*>(&v1.y));
            float2 r0 = __half22float2(*reinterpret_cast<__half2*>(&v2.x));
            float2 r1 = __half22float2(*reinterpret_cast<__half2*>(&v2.y));
            float2 s0 = __half22float2(*reinterpret_cast<__half2*>(&v3.x));
            float2 s1 = __half22float2(*reinterpret_cast<__half2*>(&v3.y));
            a0.x += w0 * p0.x; a0.y += w0 * p0.y; a0.z += w0 * p1.x; a0.w += w0 * p1.y;
            a1.x += w1 * q0.x; a1.y += w1 * q0.y; a1.z += w1 * q1.x; a1.w += w1 * q1.y;
            a2.x += w2 * r0.x; a2.y += w2 * r0.y; a2.z += w2 * r1.x; a2.w += w2 * r1.y;
            a3.x += w3 * s0.x; a3.y += w3 * s0.y; a3.z += w3 * s1.x; a3.w += w3 * s1.y;
        }
        for (; s < len; s++) {
            float w0 = attn_s[s];
            uint2 v0 = xb[(size_t)s * (En / 4) + tid];
            float2 p0 = __half22float2(*reinterpret_cast<__half2*>(&v0.x));
            float2 p1 = __half22float2(*reinterpret_cast<__half2*>(&v0.y));
            a0.x += w0 * p0.x; a0.y += w0 * p0.y; a0.z += w0 * p1.x; a0.w += w0 * p1.y;
        }
        a0.x += a1.x + a2.x + a3.x;
        a0.y += a1.y + a2.y + a3.y;
        a0.z += a1.z + a2.z + a3.z;
        a0.w += a1.w + a2.w + a3.w;
        reinterpret_cast<float4*>(out)[(size_t)b * (En / 4) + tid] = a0;
    }

    // keep_attention (last batch only): zeros outside the bag
    if (b == Bn - 1 && tid < Sn) {
        int r = tid - start;
        out[(size_t)Bn * En + tid] = (r >= 0 && r < len) ? attn_s[r] : 0.0f;
    }
}

// ---------------------------------------------------------------------------
extern "C" void kernel_launch(void* const* d_in, const int* in_sizes, int n_in,
                              void* d_out, int out_size) {
    const float* x   = (const float*)d_in[0];
    const float* W   = (const float*)d_in[1];
    const float* u   = (const float*)d_in[2];
    const int*   doc = (const int*)d_in[3];
    float* out = (float*)d_out;

    conv_kernel<<<WCONV + Bn * XBLK + 1, 256>>>((const float4*)W, (const float4*)x, doc);

    cudaFuncSetAttribute(gemm_kernel,
                         cudaFuncAttributeMaxDynamicSharedMemorySize, SMEM_TOTAL);
    gemm_kernel<<<GEMM_GRID, NTHR, SMEM_TOTAL>>>(u);

    finish_kernel<<<Bn, 256>>>(doc, out);
}